// round 16
// baseline (speedup 1.0000x reference)
#include <cuda_runtime.h>

#define B_SZ 32
#define S_LEN 2048
#define D_MODEL 1024
#define NSTATE 256
#define LN_EPS 1e-5f

__device__ float g_u[B_SZ * S_LEN];
__device__ float g_s[B_SZ * S_LEN];

__device__ __forceinline__ float warp_sum(float v) {
    #pragma unroll
    for (int o = 16; o; o >>= 1) v += __shfl_xor_sync(0xffffffffu, v, o);
    return v;
}

// Kernel 1: u[b,s] = mean_k x[b,s,k].  One warp per row of 1024.  (at DRAM roofline)
__global__ void mean_kernel(const float* __restrict__ x) {
    int gwarp = (blockIdx.x * blockDim.x + threadIdx.x) >> 5;
    int lane  = threadIdx.x & 31;
    const float4* xp = (const float4*)(x + (size_t)gwarp * D_MODEL);
    float s = 0.f;
    #pragma unroll
    for (int k = 0; k < 8; k++) {
        float4 v = xp[lane + 32 * k];
        s += (v.x + v.y) + (v.z + v.w);
    }
    s = warp_sum(s);
    if (lane == 0) g_u[gwarp] = s * (1.0f / (float)D_MODEL);
}

// Kernel 2: sequential scan, one warp per batch, 8 states/lane.
// 2-step analytic lookahead; 8 channels; flat butterfly; c1s carried across groups.
// Butterfly-independent work (T0 terms, cst2 vector) hoisted before the butterfly
// to fill the SHFL chain's latency shadow.
__global__ void __launch_bounds__(32, 1) scan_kernel(
                            const float* __restrict__ llr,
                            const float* __restrict__ logb,
                            const float* __restrict__ cvec,
                            const float* __restrict__ logstep,
                            const float* __restrict__ lngamma,
                            const float* __restrict__ lnbeta) {
    __shared__ float su[S_LEN + 4];
    __shared__ float ss[S_LEN];
    const int b = blockIdx.x;
    const int lane = threadIdx.x;
    const bool is0 = (lane == 0);

    // Stage this batch's u row into SMEM; zero pad.
    {
        const float4* up = (const float4*)(g_u + (size_t)b * S_LEN);
        float4* sp = (float4*)su;
        #pragma unroll
        for (int k = 0; k < 16; k++) sp[lane + 32 * k] = up[lane + 32 * k];
        if (lane < 4) su[S_LEN + lane] = 0.0f;
    }
    __syncwarp();

    const float step = expf(logstep[0]);
    float A[8], AB[8], BD[8], GC[8], z[8], c1s[8];
    float pgc=0.f, pbc=0.f, pca=0.f, pca2=0.f, pgca=0.f, pcab=0.f, pcbd=0.f,
          pgcab=0.f, pgcbd=0.f, pcaab=0.f, pcabd=0.f, pab2=0.f, pabbd=0.f, pbd2=0.f;
    #pragma unroll
    for (int j = 0; j < 8; j++) {
        int i = lane + 32 * j;
        float lam = -expf(llr[i]);
        float ad  = (2.0f + step * lam) / (2.0f - step * lam);
        float bb  = expf(logb[i]);
        float bd  = step * (1.0f + ad) * bb * 0.5f;
        float g   = lngamma[i];
        float be  = lnbeta[i];
        float cc  = cvec[i];
        float a   = ad * g;
        float ab  = ad * be;
        float gc  = g * cc;
        A[j]=a; AB[j]=ab; BD[j]=bd; GC[j]=gc;
        pgc  += gc;        pbc  += be*cc;
        pca  += a;         pca2 += a*a;      pgca += gc*a;
        pcab += ab;        pcbd += bd;
        pgcab+= gc*ab;     pgcbd+= gc*bd;
        pcaab+= a*ab;      pcabd+= a*bd;
        pab2 += ab*ab;     pabbd+= ab*bd;    pbd2 += bd*bd;
    }
    const float Sgc   = warp_sum(pgc);
    const float Sbc   = warp_sum(pbc);
    const float Ca    = warp_sum(pca);
    const float Ca2   = warp_sum(pca2);
    const float Cgca  = warp_sum(pgca);
    const float Cab   = warp_sum(pcab);
    const float Cbd   = warp_sum(pcbd);
    const float Cgcab = warp_sum(pgcab);
    const float Cgcbd = warp_sum(pgcbd);
    const float Caab  = warp_sum(pcaab);
    const float Cabd  = warp_sum(pcabd);
    const float Cab2  = warp_sum(pab2);
    const float Cabbd = warp_sum(pabbd);
    const float Cbd2  = warp_sum(pbd2);

    __syncwarp();
    {
        float u0 = su[0];
        float u1 = su[1];
        #pragma unroll
        for (int j = 0; j < 8; j++) {
            z[j]   = BD[j] * u0;                    // h0 = 0
            c1s[j] = fmaf(BD[j], u1, AB[j]);        // cc1 for first group
        }
    }

    const float invn = 1.0f / (float)NSTATE;
    for (int t = 0; t < S_LEN; t += 2) {
        float u1 = su[t + 1], u2 = su[t + 2];   // padded -> branchless

        // ── 8-channel lane-local partials over z_t (cc1 carried in c1s) ──
        float q0=0,q1=0,q2=0,q3=0,q4=0,q5=0,q6=0,q78=0;
        #pragma unroll
        for (int j = 0; j < 8; j++) {
            float zz  = z[j];
            float az  = A[j] * zz;
            q0 += zz;
            q1 = fmaf(zz, zz, q1);
            q2 = fmaf(GC[j], zz, q2);
            q3 += az;
            q4 = fmaf(A[j], az, q4);
            q5 = fmaf(az, az, q5);
            q6 = fmaf(GC[j], az, q6);
            q78 = fmaf(c1s[j], az, q78);          // sum (AB + u1*BD)*A*z
        }

        // ── butterfly-independent work hoisted into the SHFL latency shadow ──
        float T0   = fmaf(u1 * u1, Cbd2, fmaf(2.0f * u1, Cabbd, Cab2));
        float KS1  = fmaf(Cbd, u1, Cab);          // const part of S1n
        float KS3  = fmaf(Cgcbd, u1, Cgcab);      // const part of S3n
        float KT1  = fmaf(u1, Cabd, Caab);        // mu multiplier in T1
        float cst2[8];
        #pragma unroll
        for (int j = 0; j < 8; j++) cst2[j] = fmaf(BD[j], u2, AB[j]);

        // ── one FLAT butterfly, 8 channels (ILP hides SHFL latency) ──
        #pragma unroll
        for (int o = 16; o; o >>= 1) {
            q0  += __shfl_xor_sync(0xffffffffu, q0,  o);
            q1  += __shfl_xor_sync(0xffffffffu, q1,  o);
            q2  += __shfl_xor_sync(0xffffffffu, q2,  o);
            q3  += __shfl_xor_sync(0xffffffffu, q3,  o);
            q4  += __shfl_xor_sync(0xffffffffu, q4,  o);
            q5  += __shfl_xor_sync(0xffffffffu, q5,  o);
            q6  += __shfl_xor_sync(0xffffffffu, q6,  o);
            q78 += __shfl_xor_sync(0xffffffffu, q78, o);
        }

        // ── step t scalars (direct) ──
        float mu  = q0 * invn;
        float var = fmaf(q1, invn, -mu * mu);
        float rs  = rsqrtf(var + LN_EPS);

        // ── step t+1 sums (analytic) ──
        float T2  = fmaf(mu * mu, Ca2, fmaf(-2.0f * mu, q4, q5));
        float T1  = q78 - mu * KT1;
        float S1n = fmaf(rs, fmaf(-mu, Ca, q3), KS1);
        float S3n = fmaf(rs, fmaf(-mu, Cgca, q6), KS3);
        float S2n = fmaf(rs * rs, T2, fmaf(2.0f * rs, T1, T0));

        float mun  = S1n * invn;
        float varn = fmaf(S2n, invn, -mun * mun);
        float rsn  = rsqrtf(varn + LN_EPS);

        if (is0) {
            ss[t]     = fmaf(rs,  fmaf(-mu,  Sgc, q2),  Sbc);
            ss[t + 1] = fmaf(rsn, fmaf(-mun, Sgc, S3n), Sbc);
        }

        // ── advance z two steps; cst2 becomes next group's cc1 (u1' = u2) ──
        float g1v = -rs * mu;
        float gnv = -rsn * mun;
        #pragma unroll
        for (int j = 0; j < 8; j++) {
            float w    = fmaf(z[j], rs, g1v);
            float z1   = fmaf(w, A[j], c1s[j]);
            float w2   = fmaf(z1, rsn, gnv);
            z[j]       = fmaf(w2, A[j], cst2[j]);
            c1s[j]     = cst2[j];
        }
    }

    __syncwarp();
    {
        float4* gp = (float4*)(g_s + (size_t)b * S_LEN);
        const float4* sp = (const float4*)ss;
        #pragma unroll
        for (int k = 0; k < 16; k++) gp[lane + 32 * k] = sp[lane + 32 * k];
    }
}

// Kernel 3: out[b,s,:] = c1 * x[b,s,:] + c2 * s[b,s].  4 rows per block (MLP=4).
__global__ void out_kernel(const float* __restrict__ x,
                           const float* __restrict__ alpha,
                           const float* __restrict__ logd,
                           float* __restrict__ out) {
    const int row0 = blockIdx.x * 4;     // 16384 blocks
    const int tid  = threadIdx.x;        // 256 threads
    float a_sig = 1.0f / (1.0f + expf(-alpha[0]));
    float dd = expf(logd[0]);
    float c1 = a_sig + (1.0f - a_sig) * dd;
    float c2 = 1.0f - a_sig;
    float c2s0 = c2 * g_s[row0];
    float c2s1 = c2 * g_s[row0 + 1];
    float c2s2 = c2 * g_s[row0 + 2];
    float c2s3 = c2 * g_s[row0 + 3];

    const float4* xp = (const float4*)(x + (size_t)row0 * D_MODEL);
    float4* op = (float4*)(out + (size_t)row0 * D_MODEL);
    float4 v0 = xp[tid];
    float4 v1 = xp[tid + 256];
    float4 v2 = xp[tid + 512];
    float4 v3 = xp[tid + 768];
    v0.x = fmaf(c1, v0.x, c2s0); v0.y = fmaf(c1, v0.y, c2s0);
    v0.z = fmaf(c1, v0.z, c2s0); v0.w = fmaf(c1, v0.w, c2s0);
    v1.x = fmaf(c1, v1.x, c2s1); v1.y = fmaf(c1, v1.y, c2s1);
    v1.z = fmaf(c1, v1.z, c2s1); v1.w = fmaf(c1, v1.w, c2s1);
    v2.x = fmaf(c1, v2.x, c2s2); v2.y = fmaf(c1, v2.y, c2s2);
    v2.z = fmaf(c1, v2.z, c2s2); v2.w = fmaf(c1, v2.w, c2s2);
    v3.x = fmaf(c1, v3.x, c2s3); v3.y = fmaf(c1, v3.y, c2s3);
    v3.z = fmaf(c1, v3.z, c2s3); v3.w = fmaf(c1, v3.w, c2s3);
    op[tid]       = v0;
    op[tid + 256] = v1;
    op[tid + 512] = v2;
    op[tid + 768] = v3;
}

extern "C" void kernel_launch(void* const* d_in, const int* in_sizes, int n_in,
                              void* d_out, int out_size) {
    const float* x        = (const float*)d_in[0];
    const float* llr      = (const float*)d_in[1];
    const float* logb     = (const float*)d_in[2];
    const float* cvec     = (const float*)d_in[3];
    const float* logd     = (const float*)d_in[4];
    const float* logstep  = (const float*)d_in[5];
    const float* alpha    = (const float*)d_in[6];
    const float* lngamma  = (const float*)d_in[7];
    const float* lnbeta   = (const float*)d_in[8];
    float* out = (float*)d_out;

    mean_kernel<<<(B_SZ * S_LEN) / 8, 256>>>(x);
    scan_kernel<<<B_SZ, 32>>>(llr, logb, cvec, logstep, lngamma, lnbeta);
    out_kernel<<<B_SZ * S_LEN / 4, 256>>>(x, alpha, logd, out);
}

// round 17
// speedup vs baseline: 1.0425x; 1.0425x over previous
#include <cuda_runtime.h>

#define B_SZ 32
#define S_LEN 2048
#define D_MODEL 1024
#define NSTATE 256
#define LN_EPS 1e-5f

#define N_CHUNK 64
#define CHUNK_T 32
#define ROWS_PER_CHUNK (B_SZ * CHUNK_T)   // 1024
#define N_WORKER_BLK 116
#define N_WORKER_WARP (N_WORKER_BLK * 8)  // 928
#define GRID_TOTAL (B_SZ + N_WORKER_BLK)  // 148 = 1 wave

__device__ float g_u[B_SZ * S_LEN];
__device__ float g_s[B_SZ * S_LEN];
__device__ int   g_ucnt[N_CHUNK];

__device__ __forceinline__ float warp_sum(float v) {
    #pragma unroll
    for (int o = 16; o; o >>= 1) v += __shfl_xor_sync(0xffffffffu, v, o);
    return v;
}
__device__ __forceinline__ int ld_acq(const int* p) {
    int v; asm volatile("ld.acquire.gpu.global.b32 %0,[%1];" : "=r"(v) : "l"(p)); return v;
}

__global__ void init_kernel() {
    if (threadIdx.x < N_CHUNK) g_ucnt[threadIdx.x] = 0;
}

// Fused kernel: 32 scanner blocks (1 warp each) + 116 mean-worker blocks.
// Workers produce u in t-major order and EXIT (~41us); scanners consume u
// per-chunk (prefetch 1 ahead) and run the R15 scan math verbatim.
__global__ void __launch_bounds__(256, 1) fused_kernel(
    const float* __restrict__ x,
    const float* __restrict__ llr,
    const float* __restrict__ logb,
    const float* __restrict__ cvec,
    const float* __restrict__ logstep,
    const float* __restrict__ lngamma,
    const float* __restrict__ lnbeta)
{
    __shared__ float su[S_LEN + 4];
    __shared__ float ss[S_LEN];

    const int bid  = blockIdx.x;
    const int wid  = threadIdx.x >> 5;
    const int lane = threadIdx.x & 31;

    if (bid < B_SZ) {
        // ───────────── scanner block: warp 0 only, batch b = bid ─────────────
        if (wid != 0) return;
        const int b = bid;
        const bool is0 = (lane == 0);

        if (lane < 4) su[S_LEN + lane] = 0.0f;

        const float step = expf(logstep[0]);
        float A[8], AB[8], BD[8], GC[8], z[8], c1s[8];
        float pgc=0.f, pbc=0.f, pca=0.f, pca2=0.f, pgca=0.f, pcab=0.f, pcbd=0.f,
              pgcab=0.f, pgcbd=0.f, pcaab=0.f, pcabd=0.f, pab2=0.f, pabbd=0.f, pbd2=0.f;
        #pragma unroll
        for (int j = 0; j < 8; j++) {
            int i = lane + 32 * j;
            float lam = -expf(llr[i]);
            float ad  = (2.0f + step * lam) / (2.0f - step * lam);
            float bb  = expf(logb[i]);
            float bd  = step * (1.0f + ad) * bb * 0.5f;
            float g   = lngamma[i];
            float be  = lnbeta[i];
            float cc  = cvec[i];
            float a   = ad * g;
            float ab  = ad * be;
            float gc  = g * cc;
            A[j]=a; AB[j]=ab; BD[j]=bd; GC[j]=gc;
            pgc  += gc;        pbc  += be*cc;
            pca  += a;         pca2 += a*a;      pgca += gc*a;
            pcab += ab;        pcbd += bd;
            pgcab+= gc*ab;     pgcbd+= gc*bd;
            pcaab+= a*ab;      pcabd+= a*bd;
            pab2 += ab*ab;     pabbd+= ab*bd;    pbd2 += bd*bd;
        }
        const float Sgc   = warp_sum(pgc);
        const float Sbc   = warp_sum(pbc);
        const float Ca    = warp_sum(pca);
        const float Ca2   = warp_sum(pca2);
        const float Cgca  = warp_sum(pgca);
        const float Cab   = warp_sum(pcab);
        const float Cbd   = warp_sum(pcbd);
        const float Cgcab = warp_sum(pgcab);
        const float Cgcbd = warp_sum(pgcbd);
        const float Caab  = warp_sum(pcaab);
        const float Cabd  = warp_sum(pcabd);
        const float Cab2  = warp_sum(pab2);
        const float Cabbd = warp_sum(pabbd);
        const float Cbd2  = warp_sum(pbd2);

        // stage chunk 0 (whole warp polls — converged, coalesced)
        while (ld_acq(&g_ucnt[0]) < ROWS_PER_CHUNK) __nanosleep(200);
        su[lane] = g_u[(size_t)b * S_LEN + lane];
        __syncwarp();

        {
            float u0 = su[0];
            float u1 = su[1];
            #pragma unroll
            for (int j = 0; j < 8; j++) {
                z[j]   = BD[j] * u0;                 // h0 = 0
                c1s[j] = fmaf(BD[j], u1, AB[j]);     // cc1 for first group
            }
        }

        const float invn = 1.0f / (float)NSTATE;
        for (int c = 0; c < N_CHUNK; c++) {
            // prefetch next u chunk (instant once mean finishes, ~41us in)
            if (c + 1 < N_CHUNK) {
                while (ld_acq(&g_ucnt[c + 1]) < ROWS_PER_CHUNK) __nanosleep(200);
                su[(c + 1) * CHUNK_T + lane] =
                    g_u[(size_t)b * S_LEN + (c + 1) * CHUNK_T + lane];
                __syncwarp();
            }

            #pragma unroll 1
            for (int g16 = 0; g16 < CHUNK_T / 2; g16++) {
                const int t = c * CHUNK_T + 2 * g16;
                float u1 = su[t + 1], u2 = su[t + 2];

                // ── 8-channel lane-local partials over z_t (cc1 carried) ──
                float q0=0,q1=0,q2=0,q3=0,q4=0,q5=0,q6=0,q78=0;
                #pragma unroll
                for (int j = 0; j < 8; j++) {
                    float zz  = z[j];
                    float az  = A[j] * zz;
                    q0 += zz;
                    q1 = fmaf(zz, zz, q1);
                    q2 = fmaf(GC[j], zz, q2);
                    q3 += az;
                    q4 = fmaf(A[j], az, q4);
                    q5 = fmaf(az, az, q5);
                    q6 = fmaf(GC[j], az, q6);
                    q78 = fmaf(c1s[j], az, q78);
                }

                // ── one flat butterfly, 8 channels ──
                #pragma unroll
                for (int o = 16; o; o >>= 1) {
                    q0  += __shfl_xor_sync(0xffffffffu, q0,  o);
                    q1  += __shfl_xor_sync(0xffffffffu, q1,  o);
                    q2  += __shfl_xor_sync(0xffffffffu, q2,  o);
                    q3  += __shfl_xor_sync(0xffffffffu, q3,  o);
                    q4  += __shfl_xor_sync(0xffffffffu, q4,  o);
                    q5  += __shfl_xor_sync(0xffffffffu, q5,  o);
                    q6  += __shfl_xor_sync(0xffffffffu, q6,  o);
                    q78 += __shfl_xor_sync(0xffffffffu, q78, o);
                }

                // ── step t scalars (direct) ──
                float mu  = q0 * invn;
                float var = fmaf(q1, invn, -mu * mu);
                float rs  = rsqrtf(var + LN_EPS);

                // ── step t+1 sums (analytic) ──
                float T2  = fmaf(mu * mu, Ca2, fmaf(-2.0f * mu, q4, q5));
                float T1  = q78 - mu * fmaf(u1, Cabd, Caab);
                float T0  = fmaf(u1 * u1, Cbd2, fmaf(2.0f * u1, Cabbd, Cab2));
                float S1n = fmaf(rs, fmaf(-mu, Ca, q3), fmaf(Cbd, u1, Cab));
                float S3n = fmaf(rs, fmaf(-mu, Cgca, q6), fmaf(Cgcbd, u1, Cgcab));
                float S2n = fmaf(rs * rs, T2, fmaf(2.0f * rs, T1, T0));

                float mun  = S1n * invn;
                float varn = fmaf(S2n, invn, -mun * mun);
                float rsn  = rsqrtf(varn + LN_EPS);

                if (is0) {
                    ss[t]     = fmaf(rs,  fmaf(-mu,  Sgc, q2),  Sbc);
                    ss[t + 1] = fmaf(rsn, fmaf(-mun, Sgc, S3n), Sbc);
                }

                // ── advance z two steps; cst2 becomes next cc1 ──
                float g1v = -rs * mu;
                float gnv = -rsn * mun;
                #pragma unroll
                for (int j = 0; j < 8; j++) {
                    float w    = fmaf(z[j], rs, g1v);
                    float z1   = fmaf(w, A[j], c1s[j]);
                    float w2   = fmaf(z1, rsn, gnv);
                    float cst2 = fmaf(BD[j], u2, AB[j]);
                    z[j]       = fmaf(w2, A[j], cst2);
                    c1s[j]     = cst2;
                }
            }
        }

        __syncwarp();
        {
            float4* gp = (float4*)(g_s + (size_t)b * S_LEN);
            const float4* sp = (const float4*)ss;
            #pragma unroll
            for (int k = 0; k < 16; k++) gp[lane + 32 * k] = sp[lane + 32 * k];
        }
        return;
    }

    // ───────────── worker block: mean in t-major order, then EXIT ─────────────
    const int wg = (bid - B_SZ) * 8 + wid;   // 0 .. 927
    for (int r = wg; r < B_SZ * S_LEN; r += N_WORKER_WARP) {
        int t = r >> 5;
        int b = r & 31;
        const float4* xp = (const float4*)(x + ((size_t)b * S_LEN + t) * D_MODEL);
        float s = 0.f;
        #pragma unroll
        for (int k = 0; k < 8; k++) {
            float4 v = xp[lane + 32 * k];
            s += (v.x + v.y) + (v.z + v.w);
        }
        s = warp_sum(s);
        if (lane == 0) {
            g_u[(size_t)b * S_LEN + t] = s * (1.0f / (float)D_MODEL);
            __threadfence();
            atomicAdd(&g_ucnt[t >> 5], 1);
        }
    }
}

// out[b,s,:] = c1 * x[b,s,:] + c2 * s[b,s].  2 rows per block (R15 form).
__global__ void out_kernel(const float* __restrict__ x,
                           const float* __restrict__ alpha,
                           const float* __restrict__ logd,
                           float* __restrict__ out) {
    const int row0 = blockIdx.x * 2;
    const int tid  = threadIdx.x;
    float a_sig = 1.0f / (1.0f + expf(-alpha[0]));
    float dd = expf(logd[0]);
    float c1 = a_sig + (1.0f - a_sig) * dd;
    float c2 = 1.0f - a_sig;
    float c2s0 = c2 * g_s[row0];
    float c2s1 = c2 * g_s[row0 + 1];

    const float4* xp0 = (const float4*)(x + (size_t)row0 * D_MODEL);
    float4* op0 = (float4*)(out + (size_t)row0 * D_MODEL);
    float4 v0 = xp0[tid];
    float4 v1 = xp0[tid + 256];
    v0.x = fmaf(c1, v0.x, c2s0);
    v0.y = fmaf(c1, v0.y, c2s0);
    v0.z = fmaf(c1, v0.z, c2s0);
    v0.w = fmaf(c1, v0.w, c2s0);
    v1.x = fmaf(c1, v1.x, c2s1);
    v1.y = fmaf(c1, v1.y, c2s1);
    v1.z = fmaf(c1, v1.z, c2s1);
    v1.w = fmaf(c1, v1.w, c2s1);
    op0[tid] = v0;
    op0[tid + 256] = v1;
}

extern "C" void kernel_launch(void* const* d_in, const int* in_sizes, int n_in,
                              void* d_out, int out_size) {
    const float* x        = (const float*)d_in[0];
    const float* llr      = (const float*)d_in[1];
    const float* logb     = (const float*)d_in[2];
    const float* cvec     = (const float*)d_in[3];
    const float* logd     = (const float*)d_in[4];
    const float* logstep  = (const float*)d_in[5];
    const float* alpha    = (const float*)d_in[6];
    const float* lngamma  = (const float*)d_in[7];
    const float* lnbeta   = (const float*)d_in[8];
    float* out = (float*)d_out;

    init_kernel<<<1, 64>>>();
    fused_kernel<<<GRID_TOTAL, 256>>>(x, llr, logb, cvec, logstep, lngamma, lnbeta);
    out_kernel<<<B_SZ * S_LEN / 2, 256>>>(x, alpha, logd, out);
}